// round 3
// baseline (speedup 1.0000x reference)
#include <cuda_runtime.h>
#include <cstdint>

// y[8192,4096] = x[8192,4096] @ Wq[4096,4096]^T + bias
// Wq = group-128 symmetric int4 fake-quant of W, pre-rounded to tf32.

#define MROWS 8192
#define KDIM  4096
#define DOUT  4096

#define NSTAGES 4
#define KC      32                 // K per stage
#define STAGE_BYTES 32768          // A 16KB + B 16KB
#define SOFF_FULL  16
#define SOFF_EMPTY 48
#define SOFF_FINAL 80
#define SOFF_BIAS  256
#define SOFF_STG   2048
#define SMEM_BYTES (SOFF_STG + NSTAGES * STAGE_BYTES)  // 133120

// idesc: dtype F32(1<<4) | atype TF32(2<<7) | btype TF32(2<<10) | (N/8)<<17 | (M/16)<<24
#define IDESC 0x10400910u

// tcgen05 is arch-SPECIFIC (sm_103a). The harness also runs a plain
// compute_103 PTX pass where those instructions are illegal — gate them.
#if defined(__CUDA_ARCH_FEAT_SM103_ALL) || defined(__CUDA_ARCH_FEAT_SM101_ALL) || \
    defined(__CUDA_ARCH_FEAT_SM100_ALL) || defined(__CUDA_ARCH_SPECIFIC__)
#define TCGEN_OK 1
#else
#define TCGEN_OK 0
#endif

__device__ float g_wq[16777216];   // 64 MiB scratch: quantized+tf32-rounded W

// ---------------- helpers ----------------
__device__ __forceinline__ uint32_t s2u(const void* p) {
    uint32_t a;
    asm("{ .reg .u64 t; cvta.to.shared.u64 t, %1; cvt.u32.u64 %0, t; }" : "=r"(a) : "l"(p));
    return a;
}
__device__ __forceinline__ float tf32r(float f) {
    uint32_t u; asm("cvt.rna.tf32.f32 %0, %1;" : "=r"(u) : "f"(f));
    return __uint_as_float(u);
}
__device__ __forceinline__ uint32_t ctarank() {
    uint32_t r; asm("mov.u32 %0, %%cluster_ctarank;" : "=r"(r)); return r;
}
__device__ __forceinline__ void mbar_init(uint32_t a, uint32_t c) {
    asm volatile("mbarrier.init.shared.b64 [%0], %1;" :: "r"(a), "r"(c) : "memory");
}
__device__ __forceinline__ void mbar_wait(uint32_t a, uint32_t p) {
    asm volatile(
        "{\n\t.reg .pred P;\n"
        "W%=:\n\t"
        "mbarrier.try_wait.parity.acquire.cluster.shared::cta.b64 P, [%0], %1, 0x989680;\n\t"
        "@!P bra W%=;\n\t}\n"
        :: "r"(a), "r"(p) : "memory");
}
// arrive on the same-offset mbarrier in cluster CTA 0
__device__ __forceinline__ void arrive_rank0(uint32_t a) {
    asm volatile(
        "{\n\t.reg .b32 r;\n\t"
        "mapa.shared::cluster.u32 r, %0, 0;\n\t"
        "mbarrier.arrive.shared::cluster.b64 _, [r];\n\t}\n"
        :: "r"(a) : "memory");
}

#if TCGEN_OK
__device__ __forceinline__ void commit_mc(uint32_t bar) {
    asm volatile(
        "tcgen05.commit.cta_group::2.mbarrier::arrive::one.shared::cluster.multicast::cluster.b64 [%0], %1;"
        :: "r"(bar), "h"((uint16_t)3) : "memory");
}
__device__ __forceinline__ void mma_tf32(uint32_t d, uint64_t ad, uint64_t bd, uint32_t en) {
    asm volatile(
        "{\n\t.reg .pred p;\n\t"
        "setp.ne.u32 p, %3, 0;\n\t"
        "tcgen05.mma.cta_group::2.kind::tf32 [%0], %1, %2, %4, {%5,%5,%5,%5,%5,%5,%5,%5}, p;\n\t}\n"
        :: "r"(d), "l"(ad), "l"(bd), "r"(en), "r"(IDESC), "r"(0u) : "memory");
}
__device__ __forceinline__ void ldtm32(uint32_t* r, uint32_t a) {
    asm volatile(
        "tcgen05.ld.sync.aligned.32x32b.x32.b32 "
        "{%0,%1,%2,%3,%4,%5,%6,%7,%8,%9,%10,%11,%12,%13,%14,%15,"
        "%16,%17,%18,%19,%20,%21,%22,%23,%24,%25,%26,%27,%28,%29,%30,%31}, [%32];"
        : "=r"(r[0]),"=r"(r[1]),"=r"(r[2]),"=r"(r[3]),"=r"(r[4]),"=r"(r[5]),"=r"(r[6]),"=r"(r[7]),
          "=r"(r[8]),"=r"(r[9]),"=r"(r[10]),"=r"(r[11]),"=r"(r[12]),"=r"(r[13]),"=r"(r[14]),"=r"(r[15]),
          "=r"(r[16]),"=r"(r[17]),"=r"(r[18]),"=r"(r[19]),"=r"(r[20]),"=r"(r[21]),"=r"(r[22]),"=r"(r[23]),
          "=r"(r[24]),"=r"(r[25]),"=r"(r[26]),"=r"(r[27]),"=r"(r[28]),"=r"(r[29]),"=r"(r[30]),"=r"(r[31])
        : "r"(a));
}
#endif

__device__ __forceinline__ uint64_t smem_desc(uint32_t addr) {
    // SW128, version=1(Blackwell), SBO=64, LBO=1
    return ((uint64_t)2 << 61) | ((uint64_t)1 << 46) | ((uint64_t)64 << 32) |
           ((uint64_t)1 << 16) | ((uint64_t)(addr >> 4) & 0x3FFF);
}
__device__ __forceinline__ void sts128(uint32_t a, float x, float y, float z, float w) {
    asm volatile("st.shared.v4.b32 [%0], {%1,%2,%3,%4};"
                 :: "r"(a), "r"(__float_as_uint(x)), "r"(__float_as_uint(y)),
                    "r"(__float_as_uint(z)), "r"(__float_as_uint(w)) : "memory");
}
__device__ __forceinline__ void cluster_sync() {
    asm volatile("barrier.cluster.arrive.aligned;" ::: "memory");
    asm volatile("barrier.cluster.wait.aligned;" ::: "memory");
}

// ---------------- kernel 1: group-128 int4 fake-quant of W (+tf32 round) ----------------
__global__ __launch_bounds__(256) void quant_kernel(const float* __restrict__ w) {
    int gw   = blockIdx.x * 8 + (threadIdx.x >> 5);  // global warp id = group id
    int lane = threadIdx.x & 31;
    int row  = gw >> 5;        // W row
    int grp  = gw & 31;        // group within row
    size_t base = (size_t)row * KDIM + grp * 128 + lane * 4;
    float4 v = *(const float4*)(w + base);
    float a = fmaxf(fmaxf(fabsf(v.x), fabsf(v.y)), fmaxf(fabsf(v.z), fabsf(v.w)));
    #pragma unroll
    for (int o = 16; o; o >>= 1) a = fmaxf(a, __shfl_xor_sync(0xFFFFFFFFu, a, o));
    float scale = __fdiv_rn(a, 7.0f);
    float4 o;
    if (scale > 0.0f) {
        float qx = fminf(fmaxf(rintf(__fdiv_rn(v.x, scale)), -8.0f), 7.0f);
        float qy = fminf(fmaxf(rintf(__fdiv_rn(v.y, scale)), -8.0f), 7.0f);
        float qz = fminf(fmaxf(rintf(__fdiv_rn(v.z, scale)), -8.0f), 7.0f);
        float qw = fminf(fmaxf(rintf(__fdiv_rn(v.w, scale)), -8.0f), 7.0f);
        o.x = tf32r(__fmul_rn(qx, scale));
        o.y = tf32r(__fmul_rn(qy, scale));
        o.z = tf32r(__fmul_rn(qz, scale));
        o.w = tf32r(__fmul_rn(qw, scale));
    } else {
        o.x = o.y = o.z = o.w = 0.0f;
    }
    *(float4*)(g_wq + base) = o;
}

// ---------------- kernel 2: cg2 tf32 GEMM, 256x256 cluster tile ----------------
__global__ __launch_bounds__(288, 1) __cluster_dims__(2, 1, 1)
void gemm_kernel(const float* __restrict__ x, const float* __restrict__ bias,
                 float* __restrict__ y) {
#if TCGEN_OK
    extern __shared__ char smem[];
    uint32_t sb = s2u(smem);
    int tid = threadIdx.x, wid = tid >> 5, lane = tid & 31;
    uint32_t rank = ctarank();
    int cid = (int)(blockIdx.x >> 1);
    int n0 = (cid & 15) << 8;   // 16 n-tiles
    int m0 = (cid >> 4) << 8;   // 32 m-tiles

    if (wid == 8) {  // TMEM alloc (collective across the CTA pair)
        asm volatile("tcgen05.alloc.cta_group::2.sync.aligned.shared::cta.b32 [%0], %1;"
                     :: "r"(sb), "r"(256u) : "memory");
    }
    if (tid == 0) {
        #pragma unroll
        for (int s = 0; s < NSTAGES; s++) {
            mbar_init(sb + SOFF_FULL  + 8 * s, 16);   // 8 warps x 2 CTAs
            mbar_init(sb + SOFF_EMPTY + 8 * s, 1);    // one commit arrival
        }
        mbar_init(sb + SOFF_FINAL, 1);
    }
    if (tid < 256) ((float*)(smem + SOFF_BIAS))[tid] = bias[n0 + tid];
    __syncthreads();
    uint32_t tmem;
    asm volatile("ld.shared.b32 %0, [%1];" : "=r"(tmem) : "r"(sb));
    cluster_sync();  // barriers visible cluster-wide before any cross-CTA arrive

    if (tid < 256) {
        // ---------------- loaders: 8 warps fill A+B stages ----------------
        int   bidx[4]; uint32_t sws[4];
        #pragma unroll
        for (int i = 0; i < 4; i++) {
            int idx = tid + i * 256;
            int row = idx >> 3, c4 = idx & 7;           // 128 rows x 8 float4
            bidx[i] = row * KDIM + c4 * 4;
            uint32_t off = (uint32_t)(row * 128 + c4 * 16);
            sws[i] = off ^ ((off >> 3) & 0x70);         // SW128 swizzle
        }
        const float* Ab = x    + (size_t)(m0 + rank * 128) * KDIM;
        const float* Bb = g_wq + (size_t)(n0 + rank * 128) * KDIM;
        int st = 0, ph = 1;
        for (int kt = 0; kt < KDIM / KC; kt++) {
            mbar_wait(sb + SOFF_EMPTY + 8 * st, ph);
            int ko = kt * KC;
            float4 va[4], vb[4];
            #pragma unroll
            for (int i = 0; i < 4; i++) va[i] = __ldg((const float4*)(Ab + bidx[i] + ko));
            #pragma unroll
            for (int i = 0; i < 4; i++) vb[i] = __ldg((const float4*)(Bb + bidx[i] + ko));
            uint32_t Abase = sb + SOFF_STG + st * STAGE_BYTES;
            uint32_t Bbase = Abase + 16384;
            #pragma unroll
            for (int i = 0; i < 4; i++)
                sts128(Abase + sws[i], tf32r(va[i].x), tf32r(va[i].y), tf32r(va[i].z), tf32r(va[i].w));
            #pragma unroll
            for (int i = 0; i < 4; i++)
                sts128(Bbase + sws[i], vb[i].x, vb[i].y, vb[i].z, vb[i].w);  // pre-rounded
            __syncwarp();
            if (lane == 0) {
                asm volatile("fence.proxy.async.shared::cta;" ::: "memory");
                arrive_rank0(sb + SOFF_FULL + 8 * st);
            }
            if (++st == NSTAGES) { st = 0; ph ^= 1; }
        }
    } else if (rank == 0 && lane == 0) {
        // ---------------- MMA issuer: warp 8 lane 0 of leader CTA ----------------
        int st = 0, ph = 0;
        for (int kt = 0; kt < KDIM / KC; kt++) {
            mbar_wait(sb + SOFF_FULL + 8 * st, ph);
            uint32_t Abase = sb + SOFF_STG + st * STAGE_BYTES;
            uint64_t ad = smem_desc(Abase), bd = smem_desc(Abase + 16384);
            #pragma unroll
            for (int k = 0; k < 4; k++)           // 4 x K=8 tf32 steps per stage
                mma_tf32(tmem, ad + 2 * k, bd + 2 * k, (uint32_t)(kt | k));
            commit_mc(sb + SOFF_EMPTY + 8 * st);  // release stage in both CTAs
            if (++st == NSTAGES) { st = 0; ph ^= 1; }
        }
        commit_mc(sb + SOFF_FINAL);               // all MMAs done -> both CTAs
    }

    // ---------------- epilogue ----------------
    mbar_wait(sb + SOFF_FINAL, 0);
    asm volatile("tcgen05.fence::after_thread_sync;" ::: "memory");
    if (tid < 256) {
        int sub = wid & 3;                 // TMEM subpartition = rows sub*32+lane
        int ch  = (wid >> 2) * 128;        // column half
        size_t row = (size_t)(m0 + rank * 128 + sub * 32 + lane);
        float* yr = y + row * DOUT + n0 + ch;
        const float* bs = (const float*)(smem + SOFF_BIAS) + ch;
        #pragma unroll
        for (int cb = 0; cb < 128; cb += 32) {
            uint32_t d[32];
            ldtm32(d, tmem + ch + cb);
            asm volatile("tcgen05.wait::ld.sync.aligned;" ::: "memory");
            #pragma unroll
            for (int c = 0; c < 32; c += 4) {
                float4 o;
                o.x = __uint_as_float(d[c + 0]) + bs[cb + c + 0];
                o.y = __uint_as_float(d[c + 1]) + bs[cb + c + 1];
                o.z = __uint_as_float(d[c + 2]) + bs[cb + c + 2];
                o.w = __uint_as_float(d[c + 3]) + bs[cb + c + 3];
                *(float4*)(yr + cb + c) = o;
            }
        }
    }
    __syncthreads();
    if (wid == 8) {
        asm volatile("tcgen05.relinquish_alloc_permit.cta_group::2.sync.aligned;" ::: "memory");
        asm volatile("tcgen05.dealloc.cta_group::2.sync.aligned.b32 %0, %1;"
                     :: "r"(tmem), "r"(256u));
    }
    cluster_sync();
#else
    // ---- FFMA fallback: compiled only in the non-'a' PTX pass (never the
    // pass the GPU actually runs when an sm_103a cubin exists). Correct, slow.
    extern __shared__ char smem[];
    float* As = (float*)smem;              // 128 x 32
    float* Bs = As + 128 * 32;             // 256 x 32
    int tid = threadIdx.x;
    uint32_t rank = ctarank();
    int cid = (int)(blockIdx.x >> 1);
    int n0 = (cid & 15) << 8, m0 = (cid >> 4) << 8;
    int mbase = m0 + (int)rank * 128;
    int r0 = (tid >> 4) * 8, c0 = (tid & 15) * 16;
    float acc[8][16];
    #pragma unroll
    for (int i = 0; i < 8; i++)
        #pragma unroll
        for (int j = 0; j < 16; j++) acc[i][j] = 0.0f;
    for (int kt = 0; kt < KDIM; kt += 32) {
        __syncthreads();
        for (int idx = tid; idx < 128 * 32; idx += 288)
            As[idx] = x[(size_t)(mbase + (idx >> 5)) * KDIM + kt + (idx & 31)];
        for (int idx = tid; idx < 256 * 32; idx += 288)
            Bs[idx] = g_wq[(size_t)(n0 + (idx >> 5)) * KDIM + kt + (idx & 31)];
        __syncthreads();
        if (tid < 256) {
            for (int kk = 0; kk < 32; kk++) {
                float a[8], b[16];
                #pragma unroll
                for (int i = 0; i < 8; i++)  a[i] = As[(r0 + i) * 32 + kk];
                #pragma unroll
                for (int j = 0; j < 16; j++) b[j] = Bs[(c0 + j) * 32 + kk];
                #pragma unroll
                for (int i = 0; i < 8; i++)
                    #pragma unroll
                    for (int j = 0; j < 16; j++) acc[i][j] += a[i] * b[j];
            }
        }
    }
    if (tid < 256) {
        for (int i = 0; i < 8; i++) {
            float* yr = y + (size_t)(mbase + r0 + i) * DOUT + n0 + c0;
            #pragma unroll
            for (int j = 0; j < 16; j++) yr[j] = acc[i][j] + bias[n0 + c0 + j];
        }
    }
#endif
}

// ---------------- launch ----------------
extern "C" void kernel_launch(void* const* d_in, const int* in_sizes, int n_in,
                              void* d_out, int out_size) {
    const float* x = (const float*)d_in[0];
    const float* w = (const float*)d_in[1];
    const float* b = (const float*)d_in[2];
    float* y = (float*)d_out;

    quant_kernel<<<16384, 256>>>(w);

    cudaFuncSetAttribute(gemm_kernel, cudaFuncAttributeMaxDynamicSharedMemorySize, SMEM_BYTES);
    gemm_kernel<<<1024, 288, SMEM_BYTES>>>(x, b, y);
}

// round 4
// speedup vs baseline: 2.2777x; 2.2777x over previous
#include <cuda_runtime.h>
#include <cuda_fp16.h>
#include <cstdint>

// y[8192,4096] = x[8192,4096] @ Wq[4096,4096]^T + bias
// Wq = group-128 symmetric int4 fake-quant of W, stored fp16.
// GEMM: cg2 tcgen05 kind::f16 (fp16 operands, fp32 accum), 256x256 cluster tile.

#define MROWS 8192
#define KDIM  4096
#define DOUT  4096

#define NSTAGES 6
#define KC      64                 // K halves per stage (= 128 B per row, SW128 atom)
#define STAGE_BYTES 32768          // A 16KB + B 16KB (fp16)
#define SOFF_FULL  16              // 6 x 8B
#define SOFF_EMPTY 64              // 6 x 8B
#define SOFF_FINAL 112
#define SOFF_BIAS  256             // 256 floats
#define SOFF_STG   2048
#define SMEM_BYTES (SOFF_STG + NSTAGES * STAGE_BYTES)  // 198656

// idesc kind::f16, fp16 inputs (atype=btype=0), f32 accum: dtype F32(1<<4) | (N/8)<<17 | (M/16)<<24
#define IDESC 0x10400010u

// tcgen05 is arch-SPECIFIC: gate off for the plain compute_103 PTX pass.
#if defined(__CUDA_ARCH_FEAT_SM103_ALL) || defined(__CUDA_ARCH_FEAT_SM101_ALL) || \
    defined(__CUDA_ARCH_FEAT_SM100_ALL) || defined(__CUDA_ARCH_SPECIFIC__)
#define TCGEN_OK 1
#else
#define TCGEN_OK 0
#endif

__device__ __half g_wq[16777216];   // 32 MiB: quantized W, fp16
__device__ __half g_xh[33554432];   // 64 MiB: x converted to fp16

// ---------------- helpers ----------------
__device__ __forceinline__ uint32_t s2u(const void* p) {
    uint32_t a;
    asm("{ .reg .u64 t; cvta.to.shared.u64 t, %1; cvt.u32.u64 %0, t; }" : "=r"(a) : "l"(p));
    return a;
}
__device__ __forceinline__ uint32_t pack_h2(float lo, float hi) {
    // cvt.rn.f16x2.f32 d, a, b -> d = {hi=a, lo=b}
    uint32_t u;
    asm("cvt.rn.f16x2.f32 %0, %1, %2;" : "=r"(u) : "f"(hi), "f"(lo));
    return u;
}
__device__ __forceinline__ uint32_t ctarank() {
    uint32_t r; asm("mov.u32 %0, %%cluster_ctarank;" : "=r"(r)); return r;
}
__device__ __forceinline__ void mbar_init(uint32_t a, uint32_t c) {
    asm volatile("mbarrier.init.shared.b64 [%0], %1;" :: "r"(a), "r"(c) : "memory");
}
__device__ __forceinline__ void mbar_wait(uint32_t a, uint32_t p) {
    asm volatile(
        "{\n\t.reg .pred P;\n"
        "W%=:\n\t"
        "mbarrier.try_wait.parity.acquire.cluster.shared::cta.b64 P, [%0], %1, 0x989680;\n\t"
        "@!P bra W%=;\n\t}\n"
        :: "r"(a), "r"(p) : "memory");
}
__device__ __forceinline__ void arrive_rank0(uint32_t a) {
    asm volatile(
        "{\n\t.reg .b32 r;\n\t"
        "mapa.shared::cluster.u32 r, %0, 0;\n\t"
        "mbarrier.arrive.shared::cluster.b64 _, [r];\n\t}\n"
        :: "r"(a) : "memory");
}

#if TCGEN_OK
__device__ __forceinline__ void commit_mc(uint32_t bar) {
    asm volatile(
        "tcgen05.commit.cta_group::2.mbarrier::arrive::one.shared::cluster.multicast::cluster.b64 [%0], %1;"
        :: "r"(bar), "h"((uint16_t)3) : "memory");
}
__device__ __forceinline__ void mma_f16(uint32_t d, uint64_t ad, uint64_t bd, uint32_t en) {
    asm volatile(
        "{\n\t.reg .pred p;\n\t"
        "setp.ne.u32 p, %3, 0;\n\t"
        "tcgen05.mma.cta_group::2.kind::f16 [%0], %1, %2, %4, {%5,%5,%5,%5,%5,%5,%5,%5}, p;\n\t}\n"
        :: "r"(d), "l"(ad), "l"(bd), "r"(en), "r"(IDESC), "r"(0u) : "memory");
}
__device__ __forceinline__ void ldtm32(uint32_t* r, uint32_t a) {
    asm volatile(
        "tcgen05.ld.sync.aligned.32x32b.x32.b32 "
        "{%0,%1,%2,%3,%4,%5,%6,%7,%8,%9,%10,%11,%12,%13,%14,%15,"
        "%16,%17,%18,%19,%20,%21,%22,%23,%24,%25,%26,%27,%28,%29,%30,%31}, [%32];"
        : "=r"(r[0]),"=r"(r[1]),"=r"(r[2]),"=r"(r[3]),"=r"(r[4]),"=r"(r[5]),"=r"(r[6]),"=r"(r[7]),
          "=r"(r[8]),"=r"(r[9]),"=r"(r[10]),"=r"(r[11]),"=r"(r[12]),"=r"(r[13]),"=r"(r[14]),"=r"(r[15]),
          "=r"(r[16]),"=r"(r[17]),"=r"(r[18]),"=r"(r[19]),"=r"(r[20]),"=r"(r[21]),"=r"(r[22]),"=r"(r[23]),
          "=r"(r[24]),"=r"(r[25]),"=r"(r[26]),"=r"(r[27]),"=r"(r[28]),"=r"(r[29]),"=r"(r[30]),"=r"(r[31])
        : "r"(a));
}
#endif

__device__ __forceinline__ uint64_t smem_desc(uint32_t addr) {
    // SW128, version=1(Blackwell), SBO=64, LBO=1
    return ((uint64_t)2 << 61) | ((uint64_t)1 << 46) | ((uint64_t)64 << 32) |
           ((uint64_t)1 << 16) | ((uint64_t)(addr >> 4) & 0x3FFF);
}
__device__ __forceinline__ void sts128(uint32_t a, uint4 v) {
    asm volatile("st.shared.v4.b32 [%0], {%1,%2,%3,%4};"
                 :: "r"(a), "r"(v.x), "r"(v.y), "r"(v.z), "r"(v.w) : "memory");
}
__device__ __forceinline__ void cluster_sync() {
    asm volatile("barrier.cluster.arrive.aligned;" ::: "memory");
    asm volatile("barrier.cluster.wait.aligned;" ::: "memory");
}

// ---------------- kernel 1: group-128 int4 fake-quant of W -> fp16 ----------------
__global__ __launch_bounds__(256) void quant_kernel(const float* __restrict__ w) {
    int gw   = blockIdx.x * 8 + (threadIdx.x >> 5);  // global warp id = quant group
    int lane = threadIdx.x & 31;
    int row  = gw >> 5;
    int grp  = gw & 31;
    size_t base = (size_t)row * KDIM + grp * 128 + lane * 4;
    float4 v = *(const float4*)(w + base);
    float a = fmaxf(fmaxf(fabsf(v.x), fabsf(v.y)), fmaxf(fabsf(v.z), fabsf(v.w)));
    #pragma unroll
    for (int o = 16; o; o >>= 1) a = fmaxf(a, __shfl_xor_sync(0xFFFFFFFFu, a, o));
    float scale = __fdiv_rn(a, 7.0f);
    float ox = 0.f, oy = 0.f, oz = 0.f, ow = 0.f;
    if (scale > 0.0f) {
        ox = __fmul_rn(fminf(fmaxf(rintf(__fdiv_rn(v.x, scale)), -8.0f), 7.0f), scale);
        oy = __fmul_rn(fminf(fmaxf(rintf(__fdiv_rn(v.y, scale)), -8.0f), 7.0f), scale);
        oz = __fmul_rn(fminf(fmaxf(rintf(__fdiv_rn(v.z, scale)), -8.0f), 7.0f), scale);
        ow = __fmul_rn(fminf(fmaxf(rintf(__fdiv_rn(v.w, scale)), -8.0f), 7.0f), scale);
    }
    uint2 o; o.x = pack_h2(ox, oy); o.y = pack_h2(oz, ow);
    *(uint2*)((char*)g_wq + base * 2) = o;
}

// ---------------- kernel 1b: x fp32 -> fp16 ----------------
__global__ __launch_bounds__(256) void xconv_kernel(const float* __restrict__ x) {
    size_t i = ((size_t)blockIdx.x * 256 + threadIdx.x) * 8;
    float4 v0 = *(const float4*)(x + i);
    float4 v1 = *(const float4*)(x + i + 4);
    uint4 o;
    o.x = pack_h2(v0.x, v0.y); o.y = pack_h2(v0.z, v0.w);
    o.z = pack_h2(v1.x, v1.y); o.w = pack_h2(v1.z, v1.w);
    *(uint4*)((char*)g_xh + i * 2) = o;
}

// ---------------- kernel 2: cg2 fp16 GEMM, 256x256 cluster tile ----------------
__global__ __launch_bounds__(288, 1) __cluster_dims__(2, 1, 1)
void gemm_kernel(const float* __restrict__ bias, float* __restrict__ y) {
#if TCGEN_OK
    extern __shared__ char smem[];
    uint32_t sb = s2u(smem);
    int tid = threadIdx.x, wid = tid >> 5, lane = tid & 31;
    uint32_t rank = ctarank();
    int cid = (int)(blockIdx.x >> 1);
    int n0 = (cid & 15) << 8;   // 16 n-tiles
    int m0 = (cid >> 4) << 8;   // 32 m-tiles

    if (wid == 8) {  // collective TMEM alloc across the CTA pair
        asm volatile("tcgen05.alloc.cta_group::2.sync.aligned.shared::cta.b32 [%0], %1;"
                     :: "r"(sb), "r"(256u) : "memory");
    }
    if (tid == 0) {
        #pragma unroll
        for (int s = 0; s < NSTAGES; s++) {
            mbar_init(sb + SOFF_FULL  + 8 * s, 16);   // 8 warps x 2 CTAs
            mbar_init(sb + SOFF_EMPTY + 8 * s, 1);    // one commit arrival
        }
        mbar_init(sb + SOFF_FINAL, 1);
    }
    if (tid < 256) ((float*)(smem + SOFF_BIAS))[tid] = bias[n0 + tid];
    __syncthreads();
    uint32_t tmem;
    asm volatile("ld.shared.b32 %0, [%1];" : "=r"(tmem) : "r"(sb));
    cluster_sync();  // barriers visible cluster-wide before any cross-CTA arrive

    if (tid < 256) {
        // ------ loaders: 8 warps, register double-buffered LDG -> STS ------
        int   bidx[4]; uint32_t sws[4];
        #pragma unroll
        for (int i = 0; i < 4; i++) {
            int idx = tid + i * 256;                   // sector id 0..1023
            int row = idx >> 3, sec = idx & 7;         // 128 rows x 8 x 16B
            bidx[i] = row * KDIM + sec * 8;            // halves
            uint32_t off = (uint32_t)(row * 128 + sec * 16);
            sws[i] = off ^ ((off >> 3) & 0x70);        // SW128 swizzle
        }
        const __half* Ab = g_xh + (size_t)(m0 + rank * 128) * KDIM;
        const __half* Bb = g_wq + (size_t)(n0 + rank * 128) * KDIM;
        int st = 0, ph = 1;
        uint4 A0[4], B0[4], A1[4], B1[4];
        #pragma unroll
        for (int i = 0; i < 4; i++) A0[i] = *(const uint4*)(Ab + bidx[i]);
        #pragma unroll
        for (int i = 0; i < 4; i++) B0[i] = *(const uint4*)(Bb + bidx[i]);

        #pragma unroll 1
        for (int kt = 0; kt < KDIM / KC; kt += 2) {
            {   // prefetch kt+1
                int ko = (kt + 1) * KC;
                #pragma unroll
                for (int i = 0; i < 4; i++) A1[i] = *(const uint4*)(Ab + bidx[i] + ko);
                #pragma unroll
                for (int i = 0; i < 4; i++) B1[i] = *(const uint4*)(Bb + bidx[i] + ko);
            }
            mbar_wait(sb + SOFF_EMPTY + 8 * st, ph);
            {
                uint32_t Ad = sb + SOFF_STG + st * STAGE_BYTES, Bd = Ad + 16384;
                #pragma unroll
                for (int i = 0; i < 4; i++) sts128(Ad + sws[i], A0[i]);
                #pragma unroll
                for (int i = 0; i < 4; i++) sts128(Bd + sws[i], B0[i]);
            }
            __syncwarp();
            if (lane == 0) {
                asm volatile("fence.proxy.async.shared::cta;" ::: "memory");
                arrive_rank0(sb + SOFF_FULL + 8 * st);
            }
            if (++st == NSTAGES) { st = 0; ph ^= 1; }

            {   // prefetch kt+2 (clamped; garbage load on last iter, unused)
                int ko = min(kt + 2, KDIM / KC - 1) * KC;
                #pragma unroll
                for (int i = 0; i < 4; i++) A0[i] = *(const uint4*)(Ab + bidx[i] + ko);
                #pragma unroll
                for (int i = 0; i < 4; i++) B0[i] = *(const uint4*)(Bb + bidx[i] + ko);
            }
            mbar_wait(sb + SOFF_EMPTY + 8 * st, ph);
            {
                uint32_t Ad = sb + SOFF_STG + st * STAGE_BYTES, Bd = Ad + 16384;
                #pragma unroll
                for (int i = 0; i < 4; i++) sts128(Ad + sws[i], A1[i]);
                #pragma unroll
                for (int i = 0; i < 4; i++) sts128(Bd + sws[i], B1[i]);
            }
            __syncwarp();
            if (lane == 0) {
                asm volatile("fence.proxy.async.shared::cta;" ::: "memory");
                arrive_rank0(sb + SOFF_FULL + 8 * st);
            }
            if (++st == NSTAGES) { st = 0; ph ^= 1; }
        }
    } else if (rank == 0 && lane == 0) {
        // ------ MMA issuer: warp 8 lane 0 of leader CTA ------
        int st = 0, ph = 0;
        for (int kt = 0; kt < KDIM / KC; kt++) {
            mbar_wait(sb + SOFF_FULL + 8 * st, ph);
            uint32_t Abase = sb + SOFF_STG + st * STAGE_BYTES;
            uint64_t ad = smem_desc(Abase), bd = smem_desc(Abase + 16384);
            #pragma unroll
            for (int k = 0; k < 4; k++)           // 4 x K=16 fp16 steps per stage
                mma_f16(tmem, ad + 2 * k, bd + 2 * k, (uint32_t)(kt | k));
            commit_mc(sb + SOFF_EMPTY + 8 * st);  // release stage in both CTAs
            if (++st == NSTAGES) { st = 0; ph ^= 1; }
        }
        commit_mc(sb + SOFF_FINAL);               // all MMAs done -> both CTAs
    }

    // ---------------- epilogue ----------------
    mbar_wait(sb + SOFF_FINAL, 0);
    asm volatile("tcgen05.fence::after_thread_sync;" ::: "memory");
    if (tid < 256) {
        int sub = wid & 3;                 // TMEM subpartition = rows sub*32+lane
        int ch  = (wid >> 2) * 128;        // column half
        size_t row = (size_t)(m0 + rank * 128 + sub * 32 + lane);
        float* yr = y + row * DOUT + n0 + ch;
        const float* bs = (const float*)(smem + SOFF_BIAS) + ch;
        #pragma unroll
        for (int cb = 0; cb < 128; cb += 32) {
            uint32_t d[32];
            ldtm32(d, tmem + ch + cb);
            asm volatile("tcgen05.wait::ld.sync.aligned;" ::: "memory");
            #pragma unroll
            for (int c = 0; c < 32; c += 4) {
                float4 o;
                o.x = __uint_as_float(d[c + 0]) + bs[cb + c + 0];
                o.y = __uint_as_float(d[c + 1]) + bs[cb + c + 1];
                o.z = __uint_as_float(d[c + 2]) + bs[cb + c + 2];
                o.w = __uint_as_float(d[c + 3]) + bs[cb + c + 3];
                *(float4*)(yr + cb + c) = o;
            }
        }
    }
    __syncthreads();
    if (wid == 8) {
        asm volatile("tcgen05.relinquish_alloc_permit.cta_group::2.sync.aligned;" ::: "memory");
        asm volatile("tcgen05.dealloc.cta_group::2.sync.aligned.b32 %0, %1;"
                     :: "r"(tmem), "r"(256u));
    }
    cluster_sync();
#else
    // ---- FFMA fallback for the non-'a' PTX pass (never runs on sm_103a). ----
    extern __shared__ char smem[];
    float* As = (float*)smem;              // 128 x 32
    float* Bs = As + 128 * 32;             // 256 x 32
    int tid = threadIdx.x;
    uint32_t rank = ctarank();
    int cid = (int)(blockIdx.x >> 1);
    int n0 = (cid & 15) << 8, m0 = (cid >> 4) << 8;
    int mbase = m0 + (int)rank * 128;
    int r0 = (tid >> 4) * 8, c0 = (tid & 15) * 16;
    float acc[8][16];
    #pragma unroll
    for (int i = 0; i < 8; i++)
        #pragma unroll
        for (int j = 0; j < 16; j++) acc[i][j] = 0.0f;
    for (int kt = 0; kt < KDIM; kt += 32) {
        __syncthreads();
        for (int idx = tid; idx < 128 * 32; idx += 288)
            As[idx] = __half2float(g_xh[(size_t)(mbase + (idx >> 5)) * KDIM + kt + (idx & 31)]);
        for (int idx = tid; idx < 256 * 32; idx += 288)
            Bs[idx] = __half2float(g_wq[(size_t)(n0 + (idx >> 5)) * KDIM + kt + (idx & 31)]);
        __syncthreads();
        if (tid < 256) {
            for (int kk = 0; kk < 32; kk++) {
                float a[8], b[16];
                #pragma unroll
                for (int i = 0; i < 8; i++)  a[i] = As[(r0 + i) * 32 + kk];
                #pragma unroll
                for (int j = 0; j < 16; j++) b[j] = Bs[(c0 + j) * 32 + kk];
                #pragma unroll
                for (int i = 0; i < 8; i++)
                    #pragma unroll
                    for (int j = 0; j < 16; j++) acc[i][j] += a[i] * b[j];
            }
        }
    }
    if (tid < 256) {
        for (int i = 0; i < 8; i++) {
            float* yr = y + (size_t)(mbase + r0 + i) * DOUT + n0 + c0;
            #pragma unroll
            for (int j = 0; j < 16; j++) yr[j] = acc[i][j] + bias[n0 + c0 + j];
        }
    }
#endif
}

// ---------------- launch ----------------
extern "C" void kernel_launch(void* const* d_in, const int* in_sizes, int n_in,
                              void* d_out, int out_size) {
    const float* x = (const float*)d_in[0];
    const float* w = (const float*)d_in[1];
    const float* b = (const float*)d_in[2];
    float* y = (float*)d_out;

    quant_kernel<<<16384, 256>>>(w);
    xconv_kernel<<<16384, 256>>>(x);

    cudaFuncSetAttribute(gemm_kernel, cudaFuncAttributeMaxDynamicSharedMemorySize, SMEM_BYTES);
    gemm_kernel<<<1024, 288, SMEM_BYTES>>>(b, y);
}

// round 5
// speedup vs baseline: 2.2867x; 1.0040x over previous
#include <cuda_runtime.h>
#include <cuda_fp16.h>
#include <cstdint>

// y[8192,4096] = x[8192,4096] @ Wq[4096,4096]^T + bias
// Wq = group-128 symmetric int4 fake-quant of W, stored fp16.
// GEMM: cg2 tcgen05 kind::f16 (fp16 operands, fp32 accum), 256x256 cluster tile.

#define MROWS 8192
#define KDIM  4096
#define DOUT  4096

#define NSTAGES 6
#define KC      64                 // K halves per stage (= 128 B per row, SW128 atom)
#define STAGE_BYTES 32768          // A 16KB + B 16KB (fp16)
#define SOFF_FULL  16              // 6 x 8B
#define SOFF_EMPTY 64              // 6 x 8B
#define SOFF_FINAL 112
#define SOFF_BIAS  256             // 256 floats
#define SOFF_STG   2048
#define SMEM_BYTES (SOFF_STG + NSTAGES * STAGE_BYTES)  // 198656

// idesc kind::f16, fp16 inputs (atype=btype=0), f32 accum: dtype F32(1<<4) | (N/8)<<17 | (M/16)<<24
#define IDESC 0x10400010u

// tcgen05 is arch-SPECIFIC: gate off for the plain compute_103 PTX pass.
#if defined(__CUDA_ARCH_FEAT_SM103_ALL) || defined(__CUDA_ARCH_FEAT_SM101_ALL) || \
    defined(__CUDA_ARCH_FEAT_SM100_ALL) || defined(__CUDA_ARCH_SPECIFIC__)
#define TCGEN_OK 1
#else
#define TCGEN_OK 0
#endif

__device__ __half g_wq[16777216];   // 32 MiB: quantized W, fp16
__device__ __half g_xh[33554432];   // 64 MiB: x converted to fp16

// ---------------- helpers ----------------
__device__ __forceinline__ uint32_t s2u(const void* p) {
    uint32_t a;
    asm("{ .reg .u64 t; cvta.to.shared.u64 t, %1; cvt.u32.u64 %0, t; }" : "=r"(a) : "l"(p));
    return a;
}
__device__ __forceinline__ uint32_t pack_h2(float lo, float hi) {
    // cvt.rn.f16x2.f32 d, a, b -> d = {hi=a, lo=b}
    uint32_t u;
    asm("cvt.rn.f16x2.f32 %0, %1, %2;" : "=r"(u) : "f"(hi), "f"(lo));
    return u;
}
__device__ __forceinline__ uint32_t ctarank() {
    uint32_t r; asm("mov.u32 %0, %%cluster_ctarank;" : "=r"(r)); return r;
}
__device__ __forceinline__ void mbar_init(uint32_t a, uint32_t c) {
    asm volatile("mbarrier.init.shared.b64 [%0], %1;" :: "r"(a), "r"(c) : "memory");
}
__device__ __forceinline__ void mbar_wait(uint32_t a, uint32_t p) {
    asm volatile(
        "{\n\t.reg .pred P;\n"
        "W%=:\n\t"
        "mbarrier.try_wait.parity.acquire.cluster.shared::cta.b64 P, [%0], %1, 0x989680;\n\t"
        "@!P bra W%=;\n\t}\n"
        :: "r"(a), "r"(p) : "memory");
}
__device__ __forceinline__ void arrive_rank0(uint32_t a) {
    asm volatile(
        "{\n\t.reg .b32 r;\n\t"
        "mapa.shared::cluster.u32 r, %0, 0;\n\t"
        "mbarrier.arrive.shared::cluster.b64 _, [r];\n\t}\n"
        :: "r"(a) : "memory");
}

#if TCGEN_OK
__device__ __forceinline__ void commit_mc(uint32_t bar) {
    asm volatile(
        "tcgen05.commit.cta_group::2.mbarrier::arrive::one.shared::cluster.multicast::cluster.b64 [%0], %1;"
        :: "r"(bar), "h"((uint16_t)3) : "memory");
}
__device__ __forceinline__ void mma_f16(uint32_t d, uint64_t ad, uint64_t bd, uint32_t en) {
    asm volatile(
        "{\n\t.reg .pred p;\n\t"
        "setp.ne.u32 p, %3, 0;\n\t"
        "tcgen05.mma.cta_group::2.kind::f16 [%0], %1, %2, %4, {%5,%5,%5,%5,%5,%5,%5,%5}, p;\n\t}\n"
        :: "r"(d), "l"(ad), "l"(bd), "r"(en), "r"(IDESC), "r"(0u) : "memory");
}
__device__ __forceinline__ void ldtm32(uint32_t* r, uint32_t a) {
    asm volatile(
        "tcgen05.ld.sync.aligned.32x32b.x32.b32 "
        "{%0,%1,%2,%3,%4,%5,%6,%7,%8,%9,%10,%11,%12,%13,%14,%15,"
        "%16,%17,%18,%19,%20,%21,%22,%23,%24,%25,%26,%27,%28,%29,%30,%31}, [%32];"
        : "=r"(r[0]),"=r"(r[1]),"=r"(r[2]),"=r"(r[3]),"=r"(r[4]),"=r"(r[5]),"=r"(r[6]),"=r"(r[7]),
          "=r"(r[8]),"=r"(r[9]),"=r"(r[10]),"=r"(r[11]),"=r"(r[12]),"=r"(r[13]),"=r"(r[14]),"=r"(r[15]),
          "=r"(r[16]),"=r"(r[17]),"=r"(r[18]),"=r"(r[19]),"=r"(r[20]),"=r"(r[21]),"=r"(r[22]),"=r"(r[23]),
          "=r"(r[24]),"=r"(r[25]),"=r"(r[26]),"=r"(r[27]),"=r"(r[28]),"=r"(r[29]),"=r"(r[30]),"=r"(r[31])
        : "r"(a));
}
#endif

__device__ __forceinline__ uint64_t smem_desc(uint32_t addr) {
    // SW128, version=1(Blackwell), SBO=64, LBO=1
    return ((uint64_t)2 << 61) | ((uint64_t)1 << 46) | ((uint64_t)64 << 32) |
           ((uint64_t)1 << 16) | ((uint64_t)(addr >> 4) & 0x3FFF);
}
__device__ __forceinline__ void sts128(uint32_t a, uint4 v) {
    asm volatile("st.shared.v4.b32 [%0], {%1,%2,%3,%4};"
                 :: "r"(a), "r"(v.x), "r"(v.y), "r"(v.z), "r"(v.w) : "memory");
}
__device__ __forceinline__ void cluster_sync() {
    asm volatile("barrier.cluster.arrive.aligned;" ::: "memory");
    asm volatile("barrier.cluster.wait.aligned;" ::: "memory");
}

// ---------------- kernel 1: group-128 int4 fake-quant of W -> fp16 ----------------
__global__ __launch_bounds__(256) void quant_kernel(const float* __restrict__ w) {
    int gw   = blockIdx.x * 8 + (threadIdx.x >> 5);  // global warp id = quant group
    int lane = threadIdx.x & 31;
    int row  = gw >> 5;
    int grp  = gw & 31;
    size_t base = (size_t)row * KDIM + grp * 128 + lane * 4;
    float4 v = *(const float4*)(w + base);
    float a = fmaxf(fmaxf(fabsf(v.x), fabsf(v.y)), fmaxf(fabsf(v.z), fabsf(v.w)));
    #pragma unroll
    for (int o = 16; o; o >>= 1) a = fmaxf(a, __shfl_xor_sync(0xFFFFFFFFu, a, o));
    float scale = __fdiv_rn(a, 7.0f);
    float ox = 0.f, oy = 0.f, oz = 0.f, ow = 0.f;
    if (scale > 0.0f) {
        ox = __fmul_rn(fminf(fmaxf(rintf(__fdiv_rn(v.x, scale)), -8.0f), 7.0f), scale);
        oy = __fmul_rn(fminf(fmaxf(rintf(__fdiv_rn(v.y, scale)), -8.0f), 7.0f), scale);
        oz = __fmul_rn(fminf(fmaxf(rintf(__fdiv_rn(v.z, scale)), -8.0f), 7.0f), scale);
        ow = __fmul_rn(fminf(fmaxf(rintf(__fdiv_rn(v.w, scale)), -8.0f), 7.0f), scale);
    }
    uint2 o; o.x = pack_h2(ox, oy); o.y = pack_h2(oz, ow);
    *(uint2*)((char*)g_wq + base * 2) = o;
}

// ---------------- kernel 1b: x fp32 -> fp16 ----------------
__global__ __launch_bounds__(256) void xconv_kernel(const float* __restrict__ x) {
    size_t i = ((size_t)blockIdx.x * 256 + threadIdx.x) * 8;
    float4 v0 = *(const float4*)(x + i);
    float4 v1 = *(const float4*)(x + i + 4);
    uint4 o;
    o.x = pack_h2(v0.x, v0.y); o.y = pack_h2(v0.z, v0.w);
    o.z = pack_h2(v1.x, v1.y); o.w = pack_h2(v1.z, v1.w);
    *(uint4*)((char*)g_xh + i * 2) = o;
}

// ---------------- kernel 2: cg2 fp16 GEMM, 256x256 cluster tile ----------------
__global__ __launch_bounds__(288, 1) __cluster_dims__(2, 1, 1)
void gemm_kernel(const float* __restrict__ bias, float* __restrict__ y) {
#if TCGEN_OK
    extern __shared__ char smem[];
    uint32_t sb = s2u(smem);
    int tid = threadIdx.x, wid = tid >> 5, lane = tid & 31;
    uint32_t rank = ctarank();
    int cid = (int)(blockIdx.x >> 1);
    int n0 = (cid & 15) << 8;   // 16 n-tiles
    int m0 = (cid >> 4) << 8;   // 32 m-tiles

    if (wid == 8) {  // collective TMEM alloc across the CTA pair
        asm volatile("tcgen05.alloc.cta_group::2.sync.aligned.shared::cta.b32 [%0], %1;"
                     :: "r"(sb), "r"(256u) : "memory");
    }
    if (tid == 0) {
        #pragma unroll
        for (int s = 0; s < NSTAGES; s++) {
            mbar_init(sb + SOFF_FULL  + 8 * s, 16);   // 8 warps x 2 CTAs
            mbar_init(sb + SOFF_EMPTY + 8 * s, 1);    // one commit arrival
        }
        mbar_init(sb + SOFF_FINAL, 1);
    }
    if (tid < 256) ((float*)(smem + SOFF_BIAS))[tid] = bias[n0 + tid];
    __syncthreads();
    uint32_t tmem;
    asm volatile("ld.shared.b32 %0, [%1];" : "=r"(tmem) : "r"(sb));
    cluster_sync();  // barriers visible cluster-wide before any cross-CTA arrive

    if (tid < 256) {
        // ------ loaders: 8 warps, register double-buffered LDG -> STS ------
        int   bidx[4]; uint32_t sws[4];
        #pragma unroll
        for (int i = 0; i < 4; i++) {
            int idx = tid + i * 256;                   // sector id 0..1023
            int row = idx >> 3, sec = idx & 7;         // 128 rows x 8 x 16B
            bidx[i] = row * KDIM + sec * 8;            // halves
            uint32_t off = (uint32_t)(row * 128 + sec * 16);
            sws[i] = off ^ ((off >> 3) & 0x70);        // SW128 swizzle
        }
        const __half* Ab = g_xh + (size_t)(m0 + rank * 128) * KDIM;
        const __half* Bb = g_wq + (size_t)(n0 + rank * 128) * KDIM;
        int st = 0, ph = 1;
        uint4 A0[4], B0[4], A1[4], B1[4];
        #pragma unroll
        for (int i = 0; i < 4; i++) A0[i] = *(const uint4*)(Ab + bidx[i]);
        #pragma unroll
        for (int i = 0; i < 4; i++) B0[i] = *(const uint4*)(Bb + bidx[i]);

        #pragma unroll 1
        for (int kt = 0; kt < KDIM / KC; kt += 2) {
            {   // prefetch kt+1
                int ko = (kt + 1) * KC;
                #pragma unroll
                for (int i = 0; i < 4; i++) A1[i] = *(const uint4*)(Ab + bidx[i] + ko);
                #pragma unroll
                for (int i = 0; i < 4; i++) B1[i] = *(const uint4*)(Bb + bidx[i] + ko);
            }
            mbar_wait(sb + SOFF_EMPTY + 8 * st, ph);
            {
                uint32_t Ad = sb + SOFF_STG + st * STAGE_BYTES, Bd = Ad + 16384;
                #pragma unroll
                for (int i = 0; i < 4; i++) sts128(Ad + sws[i], A0[i]);
                #pragma unroll
                for (int i = 0; i < 4; i++) sts128(Bd + sws[i], B0[i]);
            }
            __syncwarp();
            if (lane == 0) {
                asm volatile("fence.proxy.async.shared::cta;" ::: "memory");
                arrive_rank0(sb + SOFF_FULL + 8 * st);
            }
            if (++st == NSTAGES) { st = 0; ph ^= 1; }

            {   // prefetch kt+2 (clamped; garbage load on last iter, unused)
                int ko = min(kt + 2, KDIM / KC - 1) * KC;
                #pragma unroll
                for (int i = 0; i < 4; i++) A0[i] = *(const uint4*)(Ab + bidx[i] + ko);
                #pragma unroll
                for (int i = 0; i < 4; i++) B0[i] = *(const uint4*)(Bb + bidx[i] + ko);
            }
            mbar_wait(sb + SOFF_EMPTY + 8 * st, ph);
            {
                uint32_t Ad = sb + SOFF_STG + st * STAGE_BYTES, Bd = Ad + 16384;
                #pragma unroll
                for (int i = 0; i < 4; i++) sts128(Ad + sws[i], A1[i]);
                #pragma unroll
                for (int i = 0; i < 4; i++) sts128(Bd + sws[i], B1[i]);
            }
            __syncwarp();
            if (lane == 0) {
                asm volatile("fence.proxy.async.shared::cta;" ::: "memory");
                arrive_rank0(sb + SOFF_FULL + 8 * st);
            }
            if (++st == NSTAGES) { st = 0; ph ^= 1; }
        }
    } else if (rank == 0 && lane == 0) {
        // ------ MMA issuer: warp 8 lane 0 of leader CTA ------
        int st = 0, ph = 0;
        for (int kt = 0; kt < KDIM / KC; kt++) {
            mbar_wait(sb + SOFF_FULL + 8 * st, ph);
            uint32_t Abase = sb + SOFF_STG + st * STAGE_BYTES;
            uint64_t ad = smem_desc(Abase), bd = smem_desc(Abase + 16384);
            #pragma unroll
            for (int k = 0; k < 4; k++)           // 4 x K=16 fp16 steps per stage
                mma_f16(tmem, ad + 2 * k, bd + 2 * k, (uint32_t)(kt | k));
            commit_mc(sb + SOFF_EMPTY + 8 * st);  // release stage in both CTAs
            if (++st == NSTAGES) { st = 0; ph ^= 1; }
        }
        commit_mc(sb + SOFF_FINAL);               // all MMAs done -> both CTAs
    }

    // ---------------- epilogue ----------------
    mbar_wait(sb + SOFF_FINAL, 0);
    asm volatile("tcgen05.fence::after_thread_sync;" ::: "memory");
    if (tid < 256) {
        int sub = wid & 3;                 // TMEM subpartition = rows sub*32+lane
        int ch  = (wid >> 2) * 128;        // column half
        size_t row = (size_t)(m0 + rank * 128 + sub * 32 + lane);
        float* yr = y + row * DOUT + n0 + ch;
        const float* bs = (const float*)(smem + SOFF_BIAS) + ch;
        #pragma unroll
        for (int cb = 0; cb < 128; cb += 32) {
            uint32_t d[32];
            ldtm32(d, tmem + ch + cb);
            asm volatile("tcgen05.wait::ld.sync.aligned;" ::: "memory");
            #pragma unroll
            for (int c = 0; c < 32; c += 4) {
                float4 o;
                o.x = __uint_as_float(d[c + 0]) + bs[cb + c + 0];
                o.y = __uint_as_float(d[c + 1]) + bs[cb + c + 1];
                o.z = __uint_as_float(d[c + 2]) + bs[cb + c + 2];
                o.w = __uint_as_float(d[c + 3]) + bs[cb + c + 3];
                *(float4*)(yr + cb + c) = o;
            }
        }
    }
    __syncthreads();
    if (wid == 8) {
        asm volatile("tcgen05.relinquish_alloc_permit.cta_group::2.sync.aligned;" ::: "memory");
        asm volatile("tcgen05.dealloc.cta_group::2.sync.aligned.b32 %0, %1;"
                     :: "r"(tmem), "r"(256u));
    }
    cluster_sync();
#else
    // ---- FFMA fallback for the non-'a' PTX pass (never runs on sm_103a). ----
    extern __shared__ char smem[];
    float* As = (float*)smem;              // 128 x 32
    float* Bs = As + 128 * 32;             // 256 x 32
    int tid = threadIdx.x;
    uint32_t rank = ctarank();
    int cid = (int)(blockIdx.x >> 1);
    int n0 = (cid & 15) << 8, m0 = (cid >> 4) << 8;
    int mbase = m0 + (int)rank * 128;
    int r0 = (tid >> 4) * 8, c0 = (tid & 15) * 16;
    float acc[8][16];
    #pragma unroll
    for (int i = 0; i < 8; i++)
        #pragma unroll
        for (int j = 0; j < 16; j++) acc[i][j] = 0.0f;
    for (int kt = 0; kt < KDIM; kt += 32) {
        __syncthreads();
        for (int idx = tid; idx < 128 * 32; idx += 288)
            As[idx] = __half2float(g_xh[(size_t)(mbase + (idx >> 5)) * KDIM + kt + (idx & 31)]);
        for (int idx = tid; idx < 256 * 32; idx += 288)
            Bs[idx] = __half2float(g_wq[(size_t)(n0 + (idx >> 5)) * KDIM + kt + (idx & 31)]);
        __syncthreads();
        if (tid < 256) {
            for (int kk = 0; kk < 32; kk++) {
                float a[8], b[16];
                #pragma unroll
                for (int i = 0; i < 8; i++)  a[i] = As[(r0 + i) * 32 + kk];
                #pragma unroll
                for (int j = 0; j < 16; j++) b[j] = Bs[(c0 + j) * 32 + kk];
                #pragma unroll
                for (int i = 0; i < 8; i++)
                    #pragma unroll
                    for (int j = 0; j < 16; j++) acc[i][j] += a[i] * b[j];
            }
        }
    }
    if (tid < 256) {
        for (int i = 0; i < 8; i++) {
            float* yr = y + (size_t)(mbase + r0 + i) * DOUT + n0 + c0;
            #pragma unroll
            for (int j = 0; j < 16; j++) yr[j] = acc[i][j] + bias[n0 + c0 + j];
        }
    }
#endif
}

// ---------------- launch ----------------
extern "C" void kernel_launch(void* const* d_in, const int* in_sizes, int n_in,
                              void* d_out, int out_size) {
    const float* x = (const float*)d_in[0];
    const float* w = (const float*)d_in[1];
    const float* b = (const float*)d_in[2];
    float* y = (float*)d_out;

    quant_kernel<<<16384, 256>>>(w);
    xconv_kernel<<<16384, 256>>>(x);

    cudaFuncSetAttribute(gemm_kernel, cudaFuncAttributeMaxDynamicSharedMemorySize, SMEM_BYTES);
    gemm_kernel<<<1024, 288, SMEM_BYTES>>>(b, y);
}

// round 8
// speedup vs baseline: 2.8435x; 1.2435x over previous
#include <cuda_runtime.h>
#include <cuda_fp16.h>
#include <cstdint>

// y[8192,4096] = x[8192,4096] @ Wq[4096,4096]^T + bias
// Wq = group-128 symmetric int4 fake-quant of W, stored fp16.
// GEMM: cg2 tcgen05 kind::f16 (fp16 operands, fp32 accum), 256x256 cluster tile,
// cp.async.cg deep-pipelined loaders (5-stage lookahead).

#define MROWS 8192
#define KDIM  4096
#define DOUT  4096

#define NSTAGES 6
#define KC      64                 // K halves per stage (= 128 B per row, SW128 atom)
#define STAGE_BYTES 32768          // A 16KB + B 16KB (fp16)
#define SOFF_FULL  16              // 6 x 8B
#define SOFF_EMPTY 64              // 6 x 8B
#define SOFF_FINAL 112
#define SOFF_BIAS  256             // 256 floats
#define SOFF_STG   2048
#define SMEM_BYTES (SOFF_STG + NSTAGES * STAGE_BYTES)  // 198656

// idesc kind::f16, fp16 inputs, f32 accum: dtype F32(1<<4) | (N/8)<<17 | (M/16)<<24
#define IDESC 0x10400010u

// tcgen05 is arch-SPECIFIC: gate off for the plain compute_103 PTX pass.
#if defined(__CUDA_ARCH_FEAT_SM103_ALL) || defined(__CUDA_ARCH_FEAT_SM101_ALL) || \
    defined(__CUDA_ARCH_FEAT_SM100_ALL) || defined(__CUDA_ARCH_SPECIFIC__)
#define TCGEN_OK 1
#else
#define TCGEN_OK 0
#endif

__device__ __half g_wq[16777216];   // 32 MiB: quantized W, fp16
__device__ __half g_xh[33554432];   // 64 MiB: x converted to fp16

// ---------------- helpers ----------------
__device__ __forceinline__ uint32_t s2u(const void* p) {
    uint32_t a;
    asm("{ .reg .u64 t; cvta.to.shared.u64 t, %1; cvt.u32.u64 %0, t; }" : "=r"(a) : "l"(p));
    return a;
}
__device__ __forceinline__ uint32_t pack_h2(float lo, float hi) {
    uint32_t u;
    asm("cvt.rn.f16x2.f32 %0, %1, %2;" : "=r"(u) : "f"(hi), "f"(lo));
    return u;
}
__device__ __forceinline__ uint32_t ctarank() {
    uint32_t r; asm("mov.u32 %0, %%cluster_ctarank;" : "=r"(r)); return r;
}
__device__ __forceinline__ void mbar_init(uint32_t a, uint32_t c) {
    asm volatile("mbarrier.init.shared.b64 [%0], %1;" :: "r"(a), "r"(c) : "memory");
}
__device__ __forceinline__ void mbar_wait(uint32_t a, uint32_t p) {
    asm volatile(
        "{\n\t.reg .pred P;\n"
        "W%=:\n\t"
        "mbarrier.try_wait.parity.acquire.cluster.shared::cta.b64 P, [%0], %1, 0x989680;\n\t"
        "@!P bra W%=;\n\t}\n"
        :: "r"(a), "r"(p) : "memory");
}
__device__ __forceinline__ void arrive_rank0(uint32_t a) {
    asm volatile(
        "{\n\t.reg .b32 r;\n\t"
        "mapa.shared::cluster.u32 r, %0, 0;\n\t"
        "mbarrier.arrive.shared::cluster.b64 _, [r];\n\t}\n"
        :: "r"(a) : "memory");
}
__device__ __forceinline__ void cp16(uint32_t dst, const void* src) {
    asm volatile("cp.async.cg.shared.global [%0], [%1], 16;" :: "r"(dst), "l"(src) : "memory");
}

#if TCGEN_OK
__device__ __forceinline__ void commit_mc(uint32_t bar) {
    asm volatile(
        "tcgen05.commit.cta_group::2.mbarrier::arrive::one.shared::cluster.multicast::cluster.b64 [%0], %1;"
        :: "r"(bar), "h"((uint16_t)3) : "memory");
}
__device__ __forceinline__ void mma_f16(uint32_t d, uint64_t ad, uint64_t bd, uint32_t en) {
    asm volatile(
        "{\n\t.reg .pred p;\n\t"
        "setp.ne.u32 p, %3, 0;\n\t"
        "tcgen05.mma.cta_group::2.kind::f16 [%0], %1, %2, %4, {%5,%5,%5,%5,%5,%5,%5,%5}, p;\n\t}\n"
        :: "r"(d), "l"(ad), "l"(bd), "r"(en), "r"(IDESC), "r"(0u) : "memory");
}
__device__ __forceinline__ void ldtm32(uint32_t* r, uint32_t a) {
    asm volatile(
        "tcgen05.ld.sync.aligned.32x32b.x32.b32 "
        "{%0,%1,%2,%3,%4,%5,%6,%7,%8,%9,%10,%11,%12,%13,%14,%15,"
        "%16,%17,%18,%19,%20,%21,%22,%23,%24,%25,%26,%27,%28,%29,%30,%31}, [%32];"
        : "=r"(r[0]),"=r"(r[1]),"=r"(r[2]),"=r"(r[3]),"=r"(r[4]),"=r"(r[5]),"=r"(r[6]),"=r"(r[7]),
          "=r"(r[8]),"=r"(r[9]),"=r"(r[10]),"=r"(r[11]),"=r"(r[12]),"=r"(r[13]),"=r"(r[14]),"=r"(r[15]),
          "=r"(r[16]),"=r"(r[17]),"=r"(r[18]),"=r"(r[19]),"=r"(r[20]),"=r"(r[21]),"=r"(r[22]),"=r"(r[23]),
          "=r"(r[24]),"=r"(r[25]),"=r"(r[26]),"=r"(r[27]),"=r"(r[28]),"=r"(r[29]),"=r"(r[30]),"=r"(r[31])
        : "r"(a));
}
#endif

__device__ __forceinline__ uint64_t smem_desc(uint32_t addr) {
    // SW128, version=1(Blackwell), SBO=64, LBO=1
    return ((uint64_t)2 << 61) | ((uint64_t)1 << 46) | ((uint64_t)64 << 32) |
           ((uint64_t)1 << 16) | ((uint64_t)(addr >> 4) & 0x3FFF);
}
__device__ __forceinline__ void cluster_sync() {
    asm volatile("barrier.cluster.arrive.aligned;" ::: "memory");
    asm volatile("barrier.cluster.wait.aligned;" ::: "memory");
}

// ---------------- kernel 1: group-128 int4 fake-quant of W -> fp16 ----------------
__global__ __launch_bounds__(256) void quant_kernel(const float* __restrict__ w) {
    int gw   = blockIdx.x * 8 + (threadIdx.x >> 5);  // global warp id = quant group
    int lane = threadIdx.x & 31;
    int row  = gw >> 5;
    int grp  = gw & 31;
    size_t base = (size_t)row * KDIM + grp * 128 + lane * 4;
    float4 v = *(const float4*)(w + base);
    float a = fmaxf(fmaxf(fabsf(v.x), fabsf(v.y)), fmaxf(fabsf(v.z), fabsf(v.w)));
    #pragma unroll
    for (int o = 16; o; o >>= 1) a = fmaxf(a, __shfl_xor_sync(0xFFFFFFFFu, a, o));
    float scale = __fdiv_rn(a, 7.0f);
    float ox = 0.f, oy = 0.f, oz = 0.f, ow = 0.f;
    if (scale > 0.0f) {
        ox = __fmul_rn(fminf(fmaxf(rintf(__fdiv_rn(v.x, scale)), -8.0f), 7.0f), scale);
        oy = __fmul_rn(fminf(fmaxf(rintf(__fdiv_rn(v.y, scale)), -8.0f), 7.0f), scale);
        oz = __fmul_rn(fminf(fmaxf(rintf(__fdiv_rn(v.z, scale)), -8.0f), 7.0f), scale);
        ow = __fmul_rn(fminf(fmaxf(rintf(__fdiv_rn(v.w, scale)), -8.0f), 7.0f), scale);
    }
    uint2 o; o.x = pack_h2(ox, oy); o.y = pack_h2(oz, ow);
    *(uint2*)((char*)g_wq + base * 2) = o;
}

// ---------------- kernel 1b: x fp32 -> fp16 ----------------
__global__ __launch_bounds__(256) void xconv_kernel(const float* __restrict__ x) {
    size_t i = ((size_t)blockIdx.x * 256 + threadIdx.x) * 8;
    float4 v0 = *(const float4*)(x + i);
    float4 v1 = *(const float4*)(x + i + 4);
    uint4 o;
    o.x = pack_h2(v0.x, v0.y); o.y = pack_h2(v0.z, v0.w);
    o.z = pack_h2(v1.x, v1.y); o.w = pack_h2(v1.z, v1.w);
    *(uint4*)((char*)g_xh + i * 2) = o;
}

// ---------------- kernel 2: cg2 fp16 GEMM, 256x256 cluster tile ----------------
__global__ __launch_bounds__(288, 1) __cluster_dims__(2, 1, 1)
void gemm_kernel(const float* __restrict__ bias, float* __restrict__ y) {
#if TCGEN_OK
    extern __shared__ char smem[];
    uint32_t sb = s2u(smem);
    int tid = threadIdx.x, wid = tid >> 5, lane = tid & 31;
    uint32_t rank = ctarank();
    int cid = (int)(blockIdx.x >> 1);
    int n0 = (cid & 15) << 8;   // 16 n-tiles
    int m0 = (cid >> 4) << 8;   // 32 m-tiles

    if (wid == 8) {  // collective TMEM alloc across the CTA pair
        asm volatile("tcgen05.alloc.cta_group::2.sync.aligned.shared::cta.b32 [%0], %1;"
                     :: "r"(sb), "r"(256u) : "memory");
    }
    if (tid == 0) {
        #pragma unroll
        for (int s = 0; s < NSTAGES; s++) {
            mbar_init(sb + SOFF_FULL  + 8 * s, 16);   // 8 warps x 2 CTAs
            mbar_init(sb + SOFF_EMPTY + 8 * s, 1);    // one commit arrival
        }
        mbar_init(sb + SOFF_FINAL, 1);
    }
    if (tid < 256) ((float*)(smem + SOFF_BIAS))[tid] = bias[n0 + tid];
    __syncthreads();
    uint32_t tmem;
    asm volatile("ld.shared.b32 %0, [%1];" : "=r"(tmem) : "r"(sb));
    cluster_sync();  // barriers visible cluster-wide before any cross-CTA arrive

    if (tid < 256) {
        // ------ loaders: 8 warps, cp.async.cg with 5-stage lookahead ------
        int   bidx[4]; uint32_t sws[4];
        #pragma unroll
        for (int i = 0; i < 4; i++) {
            int idx = tid + i * 256;                   // sector id 0..1023
            int row = idx >> 3, sec = idx & 7;         // 128 rows x 8 x 16B
            bidx[i] = row * KDIM + sec * 8;            // element (half) offset
            uint32_t off = (uint32_t)(row * 128 + sec * 16);
            sws[i] = off ^ ((off >> 3) & 0x70);        // SW128 swizzle
        }
        const __half* Ab = g_xh + (size_t)(m0 + rank * 128) * KDIM;
        const __half* Bb = g_wq + (size_t)(n0 + rank * 128) * KDIM;
        const int NK = KDIM / KC;                       // 64 stages
        int stW = 0, phW = 1, stA = 0;
        #pragma unroll 1
        for (int kt = 0; kt < NK + 4; kt++) {
            if (kt < NK) {
                mbar_wait(sb + SOFF_EMPTY + 8 * stW, phW);
                uint32_t Ad = sb + SOFF_STG + stW * STAGE_BYTES, Bd = Ad + 16384;
                int ko = kt * KC;
                #pragma unroll
                for (int i = 0; i < 4; i++) cp16(Ad + sws[i], Ab + bidx[i] + ko);
                #pragma unroll
                for (int i = 0; i < 4; i++) cp16(Bd + sws[i], Bb + bidx[i] + ko);
                if (++stW == NSTAGES) { stW = 0; phW ^= 1; }
            }
            asm volatile("cp.async.commit_group;" ::: "memory");
            if (kt >= 4) {
                asm volatile("cp.async.wait_group 4;" ::: "memory");
                __syncwarp();
                if (lane == 0) {
                    asm volatile("fence.proxy.async.shared::cta;" ::: "memory");
                    arrive_rank0(sb + SOFF_FULL + 8 * stA);
                }
                if (++stA == NSTAGES) stA = 0;
            }
        }
    } else if (rank == 0 && lane == 0) {
        // ------ MMA issuer: warp 8 lane 0 of leader CTA ------
        int st = 0, ph = 0;
        for (int kt = 0; kt < KDIM / KC; kt++) {
            mbar_wait(sb + SOFF_FULL + 8 * st, ph);
            uint32_t Abase = sb + SOFF_STG + st * STAGE_BYTES;
            uint64_t ad = smem_desc(Abase), bd = smem_desc(Abase + 16384);
            #pragma unroll
            for (int k = 0; k < 4; k++)           // 4 x K=16 fp16 steps per stage
                mma_f16(tmem, ad + 2 * k, bd + 2 * k, (uint32_t)(kt | k));
            commit_mc(sb + SOFF_EMPTY + 8 * st);  // release stage in both CTAs
            if (++st == NSTAGES) { st = 0; ph ^= 1; }
        }
        commit_mc(sb + SOFF_FINAL);               // all MMAs done -> both CTAs
    }

    // ---------------- epilogue ----------------
    mbar_wait(sb + SOFF_FINAL, 0);
    asm volatile("tcgen05.fence::after_thread_sync;" ::: "memory");
    if (tid < 256) {
        int sub = wid & 3;                 // TMEM subpartition = rows sub*32+lane
        int ch  = (wid >> 2) * 128;        // column half
        size_t row = (size_t)(m0 + rank * 128 + sub * 32 + lane);
        float* yr = y + row * DOUT + n0 + ch;
        const float* bs = (const float*)(smem + SOFF_BIAS) + ch;
        #pragma unroll
        for (int cb = 0; cb < 128; cb += 32) {
            uint32_t d[32];
            ldtm32(d, tmem + ch + cb);
            asm volatile("tcgen05.wait::ld.sync.aligned;" ::: "memory");
            #pragma unroll
            for (int c = 0; c < 32; c += 4) {
                float4 o;
                o.x = __uint_as_float(d[c + 0]) + bs[cb + c + 0];
                o.y = __uint_as_float(d[c + 1]) + bs[cb + c + 1];
                o.z = __uint_as_float(d[c + 2]) + bs[cb + c + 2];
                o.w = __uint_as_float(d[c + 3]) + bs[cb + c + 3];
                *(float4*)(yr + cb + c) = o;
            }
        }
    }
    __syncthreads();
    if (wid == 8) {
        asm volatile("tcgen05.relinquish_alloc_permit.cta_group::2.sync.aligned;" ::: "memory");
        asm volatile("tcgen05.dealloc.cta_group::2.sync.aligned.b32 %0, %1;"
                     :: "r"(tmem), "r"(256u));
    }
    cluster_sync();
#else
    // ---- FFMA fallback for the non-'a' PTX pass (never runs on sm_103a). ----
    extern __shared__ char smem[];
    float* As = (float*)smem;              // 128 x 32
    float* Bs = As + 128 * 32;             // 256 x 32
    int tid = threadIdx.x;
    uint32_t rank = ctarank();
    int cid = (int)(blockIdx.x >> 1);
    int n0 = (cid & 15) << 8, m0 = (cid >> 4) << 8;
    int mbase = m0 + (int)rank * 128;
    int r0 = (tid >> 4) * 8, c0 = (tid & 15) * 16;
    float acc[8][16];
    #pragma unroll
    for (int i = 0; i < 8; i++)
        #pragma unroll
        for (int j = 0; j < 16; j++) acc[i][j] = 0.0f;
    for (int kt = 0; kt < KDIM; kt += 32) {
        __syncthreads();
        for (int idx = tid; idx < 128 * 32; idx += 288)
            As[idx] = __half2float(g_xh[(size_t)(mbase + (idx >> 5)) * KDIM + kt + (idx & 31)]);
        for (int idx = tid; idx < 256 * 32; idx += 288)
            Bs[idx] = __half2float(g_wq[(size_t)(n0 + (idx >> 5)) * KDIM + kt + (idx & 31)]);
        __syncthreads();
        if (tid < 256) {
            for (int kk = 0; kk < 32; kk++) {
                float a[8], b[16];
                #pragma unroll
                for (int i = 0; i < 8; i++)  a[i] = As[(r0 + i) * 32 + kk];
                #pragma unroll
                for (int j = 0; j < 16; j++) b[j] = Bs[(c0 + j) * 32 + kk];
                #pragma unroll
                for (int i = 0; i < 8; i++)
                    #pragma unroll
                    for (int j = 0; j < 16; j++) acc[i][j] += a[i] * b[j];
            }
        }
    }
    if (tid < 256) {
        for (int i = 0; i < 8; i++) {
            float* yr = y + (size_t)(mbase + r0 + i) * DOUT + n0 + c0;
            #pragma unroll
            for (int j = 0; j < 16; j++) yr[j] = acc[i][j] + bias[n0 + c0 + j];
        }
    }
#endif
}

// ---------------- launch ----------------
extern "C" void kernel_launch(void* const* d_in, const int* in_sizes, int n_in,
                              void* d_out, int out_size) {
    const float* x = (const float*)d_in[0];
    const float* w = (const float*)d_in[1];
    const float* b = (const float*)d_in[2];
    float* y = (float*)d_out;

    quant_kernel<<<16384, 256>>>(w);
    xconv_kernel<<<16384, 256>>>(x);

    cudaFuncSetAttribute(gemm_kernel, cudaFuncAttributeMaxDynamicSharedMemorySize, SMEM_BYTES);
    gemm_kernel<<<1024, 288, SMEM_BYTES>>>(b, y);
}

// round 12
// speedup vs baseline: 3.0595x; 1.0760x over previous
#include <cuda_runtime.h>
#include <cuda_fp16.h>
#include <cstdint>

// y[8192,4096] = x[8192,4096] @ Wq[4096,4096]^T + bias
// Wq = group-128 symmetric int4 fake-quant of W, stored fp16.
// GEMM: cg2 tcgen05 kind::f16, SUPERTILE 512x256 per cluster pair:
// two 256x256 MMA tiles share each B stage (halves W's L2 traffic),
// two 256-col fp32 accumulators fill all 512 TMEM columns.

#define MROWS 8192
#define KDIM  4096
#define DOUT  4096

#define NSTAGES 4
#define KC      64                 // K halves per stage (= 128 B per row, SW128 atom)
#define STAGE_BYTES 49152          // A0 16KB + A1 16KB + B 16KB (fp16)
#define SOFF_FULL  16              // 4 x 8B
#define SOFF_EMPTY 64              // 4 x 8B
#define SOFF_FINAL 112
#define SOFF_BIAS  256             // 256 floats
#define SOFF_STG   2048
#define SMEM_BYTES (SOFF_STG + NSTAGES * STAGE_BYTES)  // 198656

// idesc kind::f16, fp16 inputs, f32 accum: dtype F32(1<<4) | (N/8)<<17 | (M/16)<<24
#define IDESC 0x10400010u

// tcgen05 is arch-SPECIFIC: gate off for the plain compute_103 PTX pass.
#if defined(__CUDA_ARCH_FEAT_SM103_ALL) || defined(__CUDA_ARCH_FEAT_SM101_ALL) || \
    defined(__CUDA_ARCH_FEAT_SM100_ALL) || defined(__CUDA_ARCH_SPECIFIC__)
#define TCGEN_OK 1
#else
#define TCGEN_OK 0
#endif

__device__ __half g_wq[16777216];   // 32 MiB: quantized W, fp16
__device__ __half g_xh[33554432];   // 64 MiB: x converted to fp16

// ---------------- helpers ----------------
__device__ __forceinline__ uint32_t s2u(const void* p) {
    uint32_t a;
    asm("{ .reg .u64 t; cvta.to.shared.u64 t, %1; cvt.u32.u64 %0, t; }" : "=r"(a) : "l"(p));
    return a;
}
__device__ __forceinline__ uint32_t pack_h2(float lo, float hi) {
    uint32_t u;
    asm("cvt.rn.f16x2.f32 %0, %1, %2;" : "=r"(u) : "f"(hi), "f"(lo));
    return u;
}
__device__ __forceinline__ uint32_t ctarank() {
    uint32_t r; asm("mov.u32 %0, %%cluster_ctarank;" : "=r"(r)); return r;
}
__device__ __forceinline__ void mbar_init(uint32_t a, uint32_t c) {
    asm volatile("mbarrier.init.shared.b64 [%0], %1;" :: "r"(a), "r"(c) : "memory");
}
__device__ __forceinline__ void mbar_wait(uint32_t a, uint32_t p) {
    asm volatile(
        "{\n\t.reg .pred P;\n"
        "W%=:\n\t"
        "mbarrier.try_wait.parity.acquire.cluster.shared::cta.b64 P, [%0], %1, 0x989680;\n\t"
        "@!P bra W%=;\n\t}\n"
        :: "r"(a), "r"(p) : "memory");
}
__device__ __forceinline__ void arrive_rank0(uint32_t a) {
    asm volatile(
        "{\n\t.reg .b32 r;\n\t"
        "mapa.shared::cluster.u32 r, %0, 0;\n\t"
        "mbarrier.arrive.shared::cluster.b64 _, [r];\n\t}\n"
        :: "r"(a) : "memory");
}
__device__ __forceinline__ void cp16(uint32_t dst, const void* src) {
    asm volatile("cp.async.cg.shared.global [%0], [%1], 16;" :: "r"(dst), "l"(src) : "memory");
}

#if TCGEN_OK
__device__ __forceinline__ void commit_mc(uint32_t bar) {
    asm volatile(
        "tcgen05.commit.cta_group::2.mbarrier::arrive::one.shared::cluster.multicast::cluster.b64 [%0], %1;"
        :: "r"(bar), "h"((uint16_t)3) : "memory");
}
__device__ __forceinline__ void mma_f16(uint32_t d, uint64_t ad, uint64_t bd, uint32_t en) {
    asm volatile(
        "{\n\t.reg .pred p;\n\t"
        "setp.ne.u32 p, %3, 0;\n\t"
        "tcgen05.mma.cta_group::2.kind::f16 [%0], %1, %2, %4, {%5,%5,%5,%5,%5,%5,%5,%5}, p;\n\t}\n"
        :: "r"(d), "l"(ad), "l"(bd), "r"(en), "r"(IDESC), "r"(0u) : "memory");
}
__device__ __forceinline__ void ldtm32(uint32_t* r, uint32_t a) {
    asm volatile(
        "tcgen05.ld.sync.aligned.32x32b.x32.b32 "
        "{%0,%1,%2,%3,%4,%5,%6,%7,%8,%9,%10,%11,%12,%13,%14,%15,"
        "%16,%17,%18,%19,%20,%21,%22,%23,%24,%25,%26,%27,%28,%29,%30,%31}, [%32];"
        : "=r"(r[0]),"=r"(r[1]),"=r"(r[2]),"=r"(r[3]),"=r"(r[4]),"=r"(r[5]),"=r"(r[6]),"=r"(r[7]),
          "=r"(r[8]),"=r"(r[9]),"=r"(r[10]),"=r"(r[11]),"=r"(r[12]),"=r"(r[13]),"=r"(r[14]),"=r"(r[15]),
          "=r"(r[16]),"=r"(r[17]),"=r"(r[18]),"=r"(r[19]),"=r"(r[20]),"=r"(r[21]),"=r"(r[22]),"=r"(r[23]),
          "=r"(r[24]),"=r"(r[25]),"=r"(r[26]),"=r"(r[27]),"=r"(r[28]),"=r"(r[29]),"=r"(r[30]),"=r"(r[31])
        : "r"(a));
}
#endif

__device__ __forceinline__ uint64_t smem_desc(uint32_t addr) {
    // SW128, version=1(Blackwell), SBO=64, LBO=1
    return ((uint64_t)2 << 61) | ((uint64_t)1 << 46) | ((uint64_t)64 << 32) |
           ((uint64_t)1 << 16) | ((uint64_t)(addr >> 4) & 0x3FFF);
}
__device__ __forceinline__ void cluster_sync() {
    asm volatile("barrier.cluster.arrive.aligned;" ::: "memory");
    asm volatile("barrier.cluster.wait.aligned;" ::: "memory");
}

// ---------------- kernel 1: group-128 int4 fake-quant of W -> fp16 ----------------
__global__ __launch_bounds__(256) void quant_kernel(const float* __restrict__ w) {
    int gw   = blockIdx.x * 8 + (threadIdx.x >> 5);  // global warp id = quant group
    int lane = threadIdx.x & 31;
    int row  = gw >> 5;
    int grp  = gw & 31;
    size_t base = (size_t)row * KDIM + grp * 128 + lane * 4;
    float4 v = *(const float4*)(w + base);
    float a = fmaxf(fmaxf(fabsf(v.x), fabsf(v.y)), fmaxf(fabsf(v.z), fabsf(v.w)));
    #pragma unroll
    for (int o = 16; o; o >>= 1) a = fmaxf(a, __shfl_xor_sync(0xFFFFFFFFu, a, o));
    float scale = __fdiv_rn(a, 7.0f);
    float ox = 0.f, oy = 0.f, oz = 0.f, ow = 0.f;
    if (scale > 0.0f) {
        ox = __fmul_rn(fminf(fmaxf(rintf(__fdiv_rn(v.x, scale)), -8.0f), 7.0f), scale);
        oy = __fmul_rn(fminf(fmaxf(rintf(__fdiv_rn(v.y, scale)), -8.0f), 7.0f), scale);
        oz = __fmul_rn(fminf(fmaxf(rintf(__fdiv_rn(v.z, scale)), -8.0f), 7.0f), scale);
        ow = __fmul_rn(fminf(fmaxf(rintf(__fdiv_rn(v.w, scale)), -8.0f), 7.0f), scale);
    }
    uint2 o; o.x = pack_h2(ox, oy); o.y = pack_h2(oz, ow);
    *(uint2*)((char*)g_wq + base * 2) = o;
}

// ---------------- kernel 1b: x fp32 -> fp16 ----------------
__global__ __launch_bounds__(256) void xconv_kernel(const float* __restrict__ x) {
    size_t i = ((size_t)blockIdx.x * 256 + threadIdx.x) * 8;
    float4 v0 = *(const float4*)(x + i);
    float4 v1 = *(const float4*)(x + i + 4);
    uint4 o;
    o.x = pack_h2(v0.x, v0.y); o.y = pack_h2(v0.z, v0.w);
    o.z = pack_h2(v1.x, v1.y); o.w = pack_h2(v1.z, v1.w);
    *(uint4*)((char*)g_xh + i * 2) = o;
}

// ---------------- kernel 2: cg2 fp16 GEMM, 512x256 supertile ----------------
__global__ __launch_bounds__(288, 1) __cluster_dims__(2, 1, 1)
void gemm_kernel(const float* __restrict__ bias, float* __restrict__ y) {
#if TCGEN_OK
    extern __shared__ char smem[];
    uint32_t sb = s2u(smem);
    int tid = threadIdx.x, wid = tid >> 5, lane = tid & 31;
    uint32_t rank = ctarank();
    int cid = (int)(blockIdx.x >> 1);
    int n0 = (cid & 15) << 8;   // 16 n-supertiles (256 wide)
    int m0 = (cid >> 4) << 9;   // 16 m-supertiles (512 tall)

    if (wid == 8) {  // collective TMEM alloc: all 512 cols (two 256-col accumulators)
        asm volatile("tcgen05.alloc.cta_group::2.sync.aligned.shared::cta.b32 [%0], %1;"
                     :: "r"(sb), "r"(512u) : "memory");
    }
    if (tid == 0) {
        #pragma unroll
        for (int s = 0; s < NSTAGES; s++) {
            mbar_init(sb + SOFF_FULL  + 8 * s, 16);   // 8 warps x 2 CTAs
            mbar_init(sb + SOFF_EMPTY + 8 * s, 1);    // one commit arrival
        }
        mbar_init(sb + SOFF_FINAL, 1);
    }
    if (tid < 256) ((float*)(smem + SOFF_BIAS))[tid] = bias[n0 + tid];
    __syncthreads();
    uint32_t tmem;
    asm volatile("ld.shared.b32 %0, [%1];" : "=r"(tmem) : "r"(sb));
    cluster_sync();  // barriers visible cluster-wide before any cross-CTA arrive

    if (tid < 256) {
        // ------ loaders: 8 warps, cp.async, stage = A0 | A1 | B (16KB each) ------
        int   bidx[4]; uint32_t sws[4];
        #pragma unroll
        for (int i = 0; i < 4; i++) {
            int idx = tid + i * 256;                   // sector id 0..1023
            int row = idx >> 3, sec = idx & 7;         // 128 rows x 8 x 16B
            bidx[i] = row * KDIM + sec * 8;            // element (half) offset
            uint32_t off = (uint32_t)(row * 128 + sec * 16);
            sws[i] = off ^ ((off >> 3) & 0x70);        // SW128 swizzle
        }
        const __half* A0b = g_xh + (size_t)(m0 + rank * 128) * KDIM;         // tile0 rows
        const __half* A1b = A0b + (size_t)256 * KDIM;                         // tile1 rows
        const __half* Bb  = g_wq + (size_t)(n0 + rank * 128) * KDIM;
        const int NK = KDIM / KC;                       // 64 stages
        int stW = 0, phW = 1, stA = 0;
        #pragma unroll 1
        for (int kt = 0; kt < NK + 2; kt++) {
            if (kt < NK) {
                mbar_wait(sb + SOFF_EMPTY + 8 * stW, phW);
                uint32_t S = sb + SOFF_STG + stW * STAGE_BYTES;
                int ko = kt * KC;
                #pragma unroll
                for (int i = 0; i < 4; i++) cp16(S +         sws[i], A0b + bidx[i] + ko);
                #pragma unroll
                for (int i = 0; i < 4; i++) cp16(S + 16384 + sws[i], A1b + bidx[i] + ko);
                #pragma unroll
                for (int i = 0; i < 4; i++) cp16(S + 32768 + sws[i], Bb  + bidx[i] + ko);
                if (++stW == NSTAGES) { stW = 0; phW ^= 1; }
            }
            asm volatile("cp.async.commit_group;" ::: "memory");
            if (kt >= 2) {
                asm volatile("cp.async.wait_group 2;" ::: "memory");
                __syncwarp();
                if (lane == 0) {
                    asm volatile("fence.proxy.async.shared::cta;" ::: "memory");
                    arrive_rank0(sb + SOFF_FULL + 8 * stA);
                }
                if (++stA == NSTAGES) stA = 0;
            }
        }
    } else if (rank == 0 && lane == 0) {
        // ------ MMA issuer: two tiles per B stage ------
        int st = 0, ph = 0;
        for (int kt = 0; kt < KDIM / KC; kt++) {
            mbar_wait(sb + SOFF_FULL + 8 * st, ph);
            uint32_t S = sb + SOFF_STG + st * STAGE_BYTES;
            uint64_t ad0 = smem_desc(S), ad1 = smem_desc(S + 16384), bd = smem_desc(S + 32768);
            uint32_t en = (uint32_t)kt;
            #pragma unroll
            for (int k = 0; k < 4; k++) {          // 4 x K=16 fp16 steps per stage
                mma_f16(tmem,       ad0 + 2 * k, bd + 2 * k, en | (uint32_t)k);
                mma_f16(tmem + 256, ad1 + 2 * k, bd + 2 * k, en | (uint32_t)k);
            }
            commit_mc(sb + SOFF_EMPTY + 8 * st);   // release stage in both CTAs
            if (++st == NSTAGES) { st = 0; ph ^= 1; }
        }
        commit_mc(sb + SOFF_FINAL);                // all MMAs done -> both CTAs
    }

    // ---------------- epilogue: 2 tiles x 4 subpartitions ----------------
    mbar_wait(sb + SOFF_FINAL, 0);
    asm volatile("tcgen05.fence::after_thread_sync;" ::: "memory");
    if (tid < 256) {
        int t   = wid >> 2;                // tile 0/1
        int sub = wid & 3;                 // TMEM subpartition = rows sub*32+lane
        size_t row = (size_t)(m0 + t * 256 + rank * 128 + sub * 32 + lane);
        float* yr = y + row * DOUT + n0;
        const float* bs = (const float*)(smem + SOFF_BIAS);
        uint32_t tbase = tmem + (uint32_t)(t * 256);
        #pragma unroll
        for (int cb = 0; cb < 256; cb += 32) {
            uint32_t d[32];
            ldtm32(d, tbase + cb);
            asm volatile("tcgen05.wait::ld.sync.aligned;" ::: "memory");
            #pragma unroll
            for (int c = 0; c < 32; c += 4) {
                float4 o;
                o.x = __uint_as_float(d[c + 0]) + bs[cb + c + 0];
                o.y = __uint_as_float(d[c + 1]) + bs[cb + c + 1];
                o.z = __uint_as_float(d[c + 2]) + bs[cb + c + 2];
                o.w = __uint_as_float(d[c + 3]) + bs[cb + c + 3];
                *(float4*)(yr + cb + c) = o;
            }
        }
    }
    __syncthreads();
    if (wid == 8) {
        asm volatile("tcgen05.relinquish_alloc_permit.cta_group::2.sync.aligned;" ::: "memory");
        asm volatile("tcgen05.dealloc.cta_group::2.sync.aligned.b32 %0, %1;"
                     :: "r"(tmem), "r"(512u));
    }
    cluster_sync();
#else
    // ---- FFMA fallback for the non-'a' PTX pass (never runs on sm_103a). ----
    extern __shared__ char smem[];
    float* As = (float*)smem;              // 512 x 16
    float* Bs = As + 512 * 16;             // 256 x 16
    int tid = threadIdx.x;
    uint32_t rank = ctarank();
    int cid = (int)(blockIdx.x >> 1);
    int n0 = (cid & 15) << 8, m0 = (cid >> 4) << 9;
    // each CTA of the pair computes half the 512 rows
    int mbase = m0 + (int)rank * 256;
    int r0 = (tid >> 4) * 16, c0 = (tid & 15) * 16;   // 16x16 per thread over 256x256
    for (int half = 0; half < 1; half++) {
        // plain tiled loop (slow, correctness-only)
    }
    if (tid < 256) {
        for (int rr = 0; rr < 16; rr++) {
            float acc[16];
            #pragma unroll
            for (int j = 0; j < 16; j++) acc[j] = 0.0f;
            size_t row = (size_t)(mbase + r0 + rr);
            for (int k = 0; k < KDIM; k++) {
                float a = __half2float(g_xh[row * KDIM + k]);
                #pragma unroll
                for (int j = 0; j < 16; j++)
                    acc[j] += a * __half2float(g_wq[(size_t)(n0 + c0 + j) * KDIM + k]);
            }
            float* yr = y + row * DOUT + n0 + c0;
            #pragma unroll
            for (int j = 0; j < 16; j++) yr[j] = acc[j] + bias[n0 + c0 + j];
        }
    }
#endif
}

// ---------------- launch ----------------
extern "C" void kernel_launch(void* const* d_in, const int* in_sizes, int n_in,
                              void* d_out, int out_size) {
    const float* x = (const float*)d_in[0];
    const float* w = (const float*)d_in[1];
    const float* b = (const float*)d_in[2];
    float* y = (float*)d_out;

    quant_kernel<<<16384, 256>>>(w);
    xconv_kernel<<<16384, 256>>>(x);

    cudaFuncSetAttribute(gemm_kernel, cudaFuncAttributeMaxDynamicSharedMemorySize, SMEM_BYTES);
    gemm_kernel<<<512, 288, SMEM_BYTES>>>(b, y);
}